// round 5
// baseline (speedup 1.0000x reference)
#include <cuda_runtime.h>
#include <cuda_bf16.h>
#include <cstdint>

#define B_TOK 4096
#define D_DIM 1024
#define O_DIM 1024
#define E_EXP 8
#define H_DIM 4096
#define NSLOT (B_TOK * 2)
#define QSCALE 16256.0f          // 127 * 128
#define QINV2  (1.0f / (QSCALE * QSCALE))

// ---------------- scratch ----------------
__device__ int   g_counts[E_EXP];
__device__ int   g_off[E_EXP + 1];
__device__ int   g_eidx[NSLOT];
__device__ int   g_epos[NSLOT];
__device__ float g_ew[NSLOT];
__device__ int   g_slot[NSLOT];
__device__ int   g_perm[NSLOT];

__device__ char  g_xq1[(size_t)B_TOK * D_DIM];
__device__ char  g_xq0[(size_t)B_TOK * D_DIM];
__device__ float g_xs[B_TOK];
__device__ char  g_w1q1[(size_t)E_EXP * H_DIM * D_DIM];   // [E][N=H][K=D]
__device__ char  g_w1q0[(size_t)E_EXP * H_DIM * D_DIM];
__device__ float g_w1s[E_EXP * H_DIM];
__device__ char  g_w2q1[(size_t)E_EXP * O_DIM * H_DIM];   // [E][N=O][K=H]
__device__ char  g_w2q0[(size_t)E_EXP * O_DIM * H_DIM];
__device__ float g_w2s[E_EXP * O_DIM];
__device__ __nv_bfloat16 g_hh[(size_t)NSLOT * H_DIM];
__device__ __nv_bfloat16 g_hl[(size_t)NSLOT * H_DIM];
__device__ char  g_hq1[(size_t)NSLOT * H_DIM];
__device__ char  g_hq0[(size_t)NSLOT * H_DIM];
__device__ float g_hs[NSLOT];
__device__ float g_y2[(size_t)NSLOT * O_DIM];

// ---------------- PTX helpers ----------------
__device__ __forceinline__ uint32_t smem_u32(const void* p) {
    uint32_t a;
    asm("{ .reg .u64 t; cvta.to.shared.u64 t, %1; cvt.u32.u64 %0, t; }" : "=r"(a) : "l"(p));
    return a;
}
__device__ __forceinline__ void cpa16(uint32_t dst, const void* src) {
    asm volatile("cp.async.cg.shared.global [%0], [%1], 16;\n" :: "r"(dst), "l"(src));
}
#define CP_COMMIT() asm volatile("cp.async.commit_group;" ::: "memory")
template<int N> __device__ __forceinline__ void cp_wait() {
    asm volatile("cp.async.wait_group %0;" :: "n"(N) : "memory");
}

#define LDSM_X4(r0, r1, r2, r3, a) \
    asm volatile("ldmatrix.sync.aligned.m8n8.x4.shared.b16 {%0,%1,%2,%3}, [%4];" \
                 : "=r"(r0), "=r"(r1), "=r"(r2), "=r"(r3) : "r"(a))

__device__ __forceinline__ void mma_s8(int* c, const uint32_t* a, const uint32_t* b) {
    asm volatile(
        "mma.sync.aligned.m16n8k32.row.col.s32.s8.s8.s32 "
        "{%0,%1,%2,%3}, {%4,%5,%6,%7}, {%8,%9}, {%0,%1,%2,%3};"
        : "+r"(c[0]), "+r"(c[1]), "+r"(c[2]), "+r"(c[3])
        : "r"(a[0]), "r"(a[1]), "r"(a[2]), "r"(a[3]), "r"(b[0]), "r"(b[1]));
}

// two-digit base-128 quantization: v ~= s/16256 * (q1*128 + q0)
__device__ __forceinline__ void quant2(float v, float inv_s, char& q1, char& q0) {
    float f127 = v * inv_s * 127.f;
    int a1 = __float2int_rn(f127);
    int a0 = __float2int_rn((f127 - (float)a1) * 128.f);
    q1 = (char)a1; q0 = (char)a0;
}

// ---------------- routing ----------------
__global__ void zero_counts_kernel() {
    if (threadIdx.x < E_EXP) g_counts[threadIdx.x] = 0;
}

__global__ void router_kernel(const float* __restrict__ x,
                              const float* __restrict__ gw,
                              const float* __restrict__ gb) {
    int b = blockIdx.x, tid = threadIdx.x;
    int e = tid & 7, ds = tid >> 3;
    const float* xr = x + (size_t)b * D_DIM;
    float p = 0.f;
    #pragma unroll 4
    for (int d = ds; d < D_DIM; d += 32) p += xr[d] * gw[d * E_EXP + e];
    __shared__ float red[256];
    red[tid] = p;
    __syncthreads();
    #pragma unroll
    for (int s = 128; s >= 8; s >>= 1) {
        if (tid < s) red[tid] += red[tid + s];
        __syncthreads();
    }
    if (tid == 0) {
        float v0 = -1e30f, v1 = -1e30f; int i0 = 0, i1 = 0;
        #pragma unroll
        for (int ee = 0; ee < E_EXP; ee++) {
            float v = red[ee] + gb[ee];
            if (v > v0) { v1 = v0; i1 = i0; v0 = v; i0 = ee; }
            else if (v > v1) { v1 = v; i1 = ee; }
        }
        float ex = expf(v1 - v0), inv = 1.f / (1.f + ex);
        int p0 = atomicAdd(&g_counts[i0], 1);
        int p1 = atomicAdd(&g_counts[i1], 1);
        g_eidx[b*2+0] = i0; g_epos[b*2+0] = p0; g_ew[b*2+0] = inv;
        g_eidx[b*2+1] = i1; g_epos[b*2+1] = p1; g_ew[b*2+1] = ex * inv;
    }
}

__global__ void scan_kernel() {
    if (threadIdx.x == 0) {
        int acc = 0;
        #pragma unroll
        for (int e = 0; e < E_EXP; e++) { g_off[e] = acc; acc += g_counts[e]; }
        g_off[E_EXP] = acc;
    }
}

__global__ void scatter_kernel() {
    int i = blockIdx.x * blockDim.x + threadIdx.x;
    if (i >= NSLOT) return;
    int slot = g_off[g_eidx[i]] + g_epos[i];
    g_slot[i] = slot;
    g_perm[slot] = i >> 1;
}

// ---------------- quantization kernels ----------------
// x: per-row scale, 4096 blocks x 256 threads, 4 elems/thread
__global__ void xquant_kernel(const float* __restrict__ x) {
    int b = blockIdx.x, t = threadIdx.x;
    float4 v = *(const float4*)(x + (size_t)b * D_DIM + t * 4);
    float m = fmaxf(fmaxf(fabsf(v.x), fabsf(v.y)), fmaxf(fabsf(v.z), fabsf(v.w)));
    __shared__ float red[256];
    red[t] = m;
    __syncthreads();
    #pragma unroll
    for (int s = 128; s >= 1; s >>= 1) {
        if (t < s) red[t] = fmaxf(red[t], red[t + s]);
        __syncthreads();
    }
    float sc = fmaxf(red[0], 1e-20f);
    if (t == 0) g_xs[b] = sc;
    float inv = 1.f / sc;
    char q1[4], q0[4];
    quant2(v.x, inv, q1[0], q0[0]);
    quant2(v.y, inv, q1[1], q0[1]);
    quant2(v.z, inv, q1[2], q0[2]);
    quant2(v.w, inv, q1[3], q0[3]);
    *(char4*)(g_xq1 + (size_t)b * D_DIM + t * 4) = make_char4(q1[0], q1[1], q1[2], q1[3]);
    *(char4*)(g_xq0 + (size_t)b * D_DIM + t * 4) = make_char4(q0[0], q0[1], q0[2], q0[3]);
}

// h: reconstruct from bf16 pair, per-row scale, quantize. 1 block per slot row.
__global__ void hquant_kernel() {
    int slot = blockIdx.x, t = threadIdx.x;
    const __nv_bfloat162* hh2 = (const __nv_bfloat162*)(g_hh + (size_t)slot * H_DIM);
    const __nv_bfloat162* hl2 = (const __nv_bfloat162*)(g_hl + (size_t)slot * H_DIM);
    float v[16];
    float m = 0.f;
    #pragma unroll
    for (int i = 0; i < 8; i++) {
        __nv_bfloat162 h = hh2[t * 8 + i], l = hl2[t * 8 + i];
        v[i*2+0] = __bfloat162float(h.x) + __bfloat162float(l.x);
        v[i*2+1] = __bfloat162float(h.y) + __bfloat162float(l.y);
        m = fmaxf(m, fmaxf(fabsf(v[i*2]), fabsf(v[i*2+1])));
    }
    __shared__ float red[256];
    red[t] = m;
    __syncthreads();
    #pragma unroll
    for (int s = 128; s >= 1; s >>= 1) {
        if (t < s) red[t] = fmaxf(red[t], red[t + s]);
        __syncthreads();
    }
    float sc = fmaxf(red[0], 1e-20f);
    if (t == 0) g_hs[slot] = sc;
    float inv = 1.f / sc;
    union { char c[16]; int4 i4; } u1, u0;
    #pragma unroll
    for (int i = 0; i < 16; i++) quant2(v[i], inv, u1.c[i], u0.c[i]);
    *(int4*)(g_hq1 + (size_t)slot * H_DIM + t * 16) = u1.i4;
    *(int4*)(g_hq0 + (size_t)slot * H_DIM + t * 16) = u0.i4;
}

// weights: per-(e, out-col n) scale; quantize + transpose to [E][N][K].
// grid (ND/128, 1, E), 256 threads (tx = col 0..127, ty = 0..1).
__global__ void wquant_kernel(const float* __restrict__ w,
                              char* __restrict__ oq1, char* __restrict__ oq0,
                              float* __restrict__ oscl, int KD, int ND) {
    __shared__ float smax[256];
    __shared__ int s1w[128 * 33];   // [n][k-word] padded: bank = (n + kw) % 32
    __shared__ int s0w[128 * 33];

    int e  = blockIdx.z;
    int n0 = blockIdx.x * 128;
    int tx = threadIdx.x & 127, ty = threadIdx.x >> 7;
    const float* W = w + (size_t)e * KD * ND;

    // phase 1: column max
    float m = 0.f;
    for (int k = ty; k < KD; k += 2)
        m = fmaxf(m, fabsf(W[(size_t)k * ND + n0 + tx]));
    smax[threadIdx.x] = m;
    __syncthreads();
    if (ty == 0) {
        float sc = fmaxf(fmaxf(smax[tx], smax[tx + 128]), 1e-20f);
        smax[tx] = sc;
        oscl[e * ND + n0 + tx] = sc;
    }
    __syncthreads();
    float inv = 1.f / smax[tx];

    // phase 2: quantize + transpose, 128-k blocks
    size_t ob = (size_t)e * ND * KD;
    for (int kb = 0; kb < KD; kb += 128) {
        for (int kg = ty; kg < 32; kg += 2) {          // kg = 4-k group
            union { char c[4]; int w32; } u1, u0;
            #pragma unroll
            for (int cc = 0; cc < 4; cc++) {
                float vv = W[(size_t)(kb + kg * 4 + cc) * ND + n0 + tx];
                quant2(vv, inv, u1.c[cc], u0.c[cc]);
            }
            s1w[tx * 33 + kg] = u1.w32;
            s0w[tx * 33 + kg] = u0.w32;
        }
        __syncthreads();
        #pragma unroll
        for (int t = 0; t < 16; t++) {
            int j = threadIdx.x + t * 256;             // 0..4095 words
            int row = j >> 5, kw = j & 31;
            size_t dst = ob + (size_t)(n0 + row) * KD + kb + kw * 4;
            *(int*)(oq1 + dst) = s1w[row * 33 + kw];
            *(int*)(oq0 + dst) = s0w[row * 33 + kw];
        }
        __syncthreads();
    }
}

// ---------------- IMMA grouped GEMM ----------------
// CTA 128x128xK32, 8 warps 2x4, warp tile 64x32, s8 m16n8k32, 3 digit passes.
// Stage = A1 4K | A0 4K | B1 4K | B0 4K = 16KB; 6 stages = 96KB.
#define STAGES 6
#define STAGE_BYTES 16384
#define GEMM_SMEM (STAGES * STAGE_BYTES)

template <int MODE>
__global__ __launch_bounds__(256, 1)
void moe_gemm_imma(const char* __restrict__ Aq1, const char* __restrict__ Aq0,
                   const float* __restrict__ Ascl,
                   const char* __restrict__ Wq1, const char* __restrict__ Wq0,
                   const float* __restrict__ Wscl,
                   const float* __restrict__ bias,
                   float* __restrict__ yout,
                   int KD, int ND) {
    int e   = blockIdx.z;
    int cnt = g_counts[e];
    int m0  = blockIdx.y * 128;
    if (m0 >= cnt) return;
    int off = g_off[e];
    int n0  = blockIdx.x * 128;

    extern __shared__ char dsm[];
    __shared__ int   s_arow[128];
    __shared__ float s_ascl[128];

    int tid  = threadIdx.x;
    int wid  = tid >> 5, lane = tid & 31;
    int wm   = (wid >> 2) * 64;
    int wn   = (wid & 3) * 32;
    int g    = lane >> 2, t4 = lane & 3;

    const char* W1 = Wq1 + (size_t)e * ND * KD;
    const char* W0 = Wq0 + (size_t)e * ND * KD;

    if (tid < 128) {
        int r = m0 + tid;
        int src = 0;
        if (r < cnt) src = (MODE == 0) ? g_perm[off + r] : (off + r);
        s_arow[tid] = src;
        s_ascl[tid] = Ascl[src];
    }
    __syncthreads();

    uint32_t smb = smem_u32(dsm);
    const int NC = KD >> 5;

    auto load_stage = [&](int c) {
        uint32_t sb = smb + (c % STAGES) * STAGE_BYTES;
        int k0 = c << 5;
        #pragma unroll
        for (int i = 0; i < 4; i++) {
            int cid = tid + i * 256;                    // 0..1023
            int half  = cid >> 9;                       // 0 = A, 1 = B
            int sub   = cid & 511;
            int digit = (sub >> 8) & 1;                 // 0 = q1, 1 = q0
            int s     = sub & 255;
            int row   = s >> 1, kseg = s & 1;
            uint32_t so = (uint32_t)(row * 32 + ((kseg ^ ((row >> 2) & 1)) << 4));
            if (half == 0) {
                const char* src = (digit ? Aq0 : Aq1) + (size_t)s_arow[row] * KD + k0 + kseg * 16;
                cpa16(sb + digit * 4096 + so, src);
            } else {
                const char* src = (digit ? W0 : W1) + (size_t)(n0 + row) * KD + k0 + kseg * 16;
                cpa16(sb + 8192 + digit * 4096 + so, src);
            }
        }
        CP_COMMIT();
    };

    #pragma unroll
    for (int s = 0; s < STAGES; s++) load_stage(s);

    int acc2[4][4][4], acc1[4][4][4];
    #pragma unroll
    for (int i = 0; i < 4; i++)
        #pragma unroll
        for (int j = 0; j < 4; j++)
            #pragma unroll
            for (int q = 0; q < 4; q++) { acc2[i][j][q] = 0; acc1[i][j][q] = 0; }

    for (int c = 0; c < NC; c++) {
        int L = NC - c - 1; if (L > STAGES - 1) L = STAGES - 1;
        switch (L) {
            case 5: cp_wait<5>(); break;
            case 4: cp_wait<4>(); break;
            case 3: cp_wait<3>(); break;
            case 2: cp_wait<2>(); break;
            case 1: cp_wait<1>(); break;
            default: cp_wait<0>(); break;
        }
        __syncthreads();
        uint32_t sb = smb + (c % STAGES) * STAGE_BYTES;

        // B fragments: 2 octpairs x (q1,q0); regs [b0_octL, b1_octL, b0_octH, b1_octH]
        uint32_t B1r[8], B0r[8];
        #pragma unroll
        for (int op = 0; op < 2; op++) {
            int n_l = wn + op * 16 + ((lane >> 4) << 3) + (lane & 7);
            int ks  = (lane >> 3) & 1;
            uint32_t so = (uint32_t)(n_l * 32 + ((ks ^ ((n_l >> 2) & 1)) << 4));
            LDSM_X4(B1r[op*4+0], B1r[op*4+1], B1r[op*4+2], B1r[op*4+3], sb + 8192 + so);
            LDSM_X4(B0r[op*4+0], B0r[op*4+1], B0r[op*4+2], B0r[op*4+3], sb + 12288 + so);
        }
        #pragma unroll
        for (int mf = 0; mf < 4; mf++) {
            int row_l = wm + mf * 16 + (lane & 15);
            int ks    = lane >> 4;
            uint32_t so = (uint32_t)(row_l * 32 + ((ks ^ ((row_l >> 2) & 1)) << 4));
            uint32_t a1[4], a0[4];
            LDSM_X4(a1[0], a1[1], a1[2], a1[3], sb + so);
            LDSM_X4(a0[0], a0[1], a0[2], a0[3], sb + 4096 + so);
            #pragma unroll
            for (int nf = 0; nf < 4; nf++) {
                mma_s8(acc2[mf][nf], a1, &B1r[nf*2]);
                mma_s8(acc1[mf][nf], a1, &B0r[nf*2]);
                mma_s8(acc1[mf][nf], a0, &B1r[nf*2]);
            }
        }
        __syncthreads();
        if (c + STAGES < NC) load_stage(c + STAGES);
    }

    // ---------------- epilogue ----------------
    float sb0[4], sb1[4], bias0[4], bias1[4];
    #pragma unroll
    for (int nf = 0; nf < 4; nf++) {
        int n = n0 + wn + nf * 8 + t4 * 2;
        float2 ws = *(const float2*)(Wscl + e * ND + n);
        sb0[nf] = ws.x; sb1[nf] = ws.y;
        float2 bs = *(const float2*)(bias + e * ND + n);
        bias0[nf] = bs.x; bias1[nf] = bs.y;
    }

    #pragma unroll
    for (int mf = 0; mf < 4; mf++) {
        #pragma unroll
        for (int half = 0; half < 2; half++) {
            int rl = wm + mf * 16 + g + half * 8;
            int r  = m0 + rl;
            if (r >= cnt) continue;
            float sa = s_ascl[rl] * QINV2;
            size_t rb = (size_t)(off + r) * ND + n0 + wn + t4 * 2;
            #pragma unroll
            for (int nf = 0; nf < 4; nf++) {
                float p20 = (float)acc2[mf][nf][half*2+0];
                float p21 = (float)acc2[mf][nf][half*2+1];
                float p10 = (float)acc1[mf][nf][half*2+0];
                float p11 = (float)acc1[mf][nf][half*2+1];
                float v0 = sa * sb0[nf] * fmaf(16384.f, p20, 128.f * p10) + bias0[nf];
                float v1 = sa * sb1[nf] * fmaf(16384.f, p21, 128.f * p11) + bias1[nf];
                if (MODE == 0) {
                    v0 = v0 > 0.f ? v0 : 0.f;
                    v1 = v1 > 0.f ? v1 : 0.f;
                    __nv_bfloat16 h0 = __float2bfloat16(v0);
                    __nv_bfloat16 h1 = __float2bfloat16(v1);
                    __nv_bfloat16 l0 = __float2bfloat16(v0 - __bfloat162float(h0));
                    __nv_bfloat16 l1 = __float2bfloat16(v1 - __bfloat162float(h1));
                    *(__nv_bfloat162*)(g_hh + rb + nf * 8) = __nv_bfloat162(h0, h1);
                    *(__nv_bfloat162*)(g_hl + rb + nf * 8) = __nv_bfloat162(l0, l1);
                } else {
                    *(float2*)(yout + rb + nf * 8) = make_float2(v0, v1);
                }
            }
        }
    }
}

// ---------------- combine ----------------
__global__ void combine_kernel(float* __restrict__ y) {
    int b = blockIdx.x, t = threadIdx.x;
    int s0 = g_slot[b*2+0], s1 = g_slot[b*2+1];
    float w0 = g_ew[b*2+0], w1 = g_ew[b*2+1];
    float4 a = *(const float4*)(g_y2 + (size_t)s0 * O_DIM + t * 4);
    float4 c = *(const float4*)(g_y2 + (size_t)s1 * O_DIM + t * 4);
    float4 o;
    o.x = w0 * a.x + w1 * c.x;
    o.y = w0 * a.y + w1 * c.y;
    o.z = w0 * a.z + w1 * c.z;
    o.w = w0 * a.w + w1 * c.w;
    *(float4*)(y + (size_t)b * O_DIM + t * 4) = o;
}

// ---------------- launch ----------------
extern "C" void kernel_launch(void* const* d_in, const int* in_sizes, int n_in,
                              void* d_out, int out_size) {
    const float* x  = (const float*)d_in[0];
    const float* gw = (const float*)d_in[1];
    const float* gb = (const float*)d_in[2];
    const float* w1 = (const float*)d_in[3];
    const float* b1 = (const float*)d_in[4];
    const float* w2 = (const float*)d_in[5];
    const float* b2 = (const float*)d_in[6];
    float* y = (float*)d_out;

    cudaFuncSetAttribute(moe_gemm_imma<0>, cudaFuncAttributeMaxDynamicSharedMemorySize, GEMM_SMEM);
    cudaFuncSetAttribute(moe_gemm_imma<1>, cudaFuncAttributeMaxDynamicSharedMemorySize, GEMM_SMEM);

    char *xq1, *xq0, *w1q1, *w1q0, *w2q1, *w2q0, *hq1, *hq0;
    float *xs, *w1s, *w2s, *hs, *y2;
    cudaGetSymbolAddress((void**)&xq1, g_xq1);
    cudaGetSymbolAddress((void**)&xq0, g_xq0);
    cudaGetSymbolAddress((void**)&xs,  g_xs);
    cudaGetSymbolAddress((void**)&w1q1, g_w1q1);
    cudaGetSymbolAddress((void**)&w1q0, g_w1q0);
    cudaGetSymbolAddress((void**)&w1s,  g_w1s);
    cudaGetSymbolAddress((void**)&w2q1, g_w2q1);
    cudaGetSymbolAddress((void**)&w2q0, g_w2q0);
    cudaGetSymbolAddress((void**)&w2s,  g_w2s);
    cudaGetSymbolAddress((void**)&hq1, g_hq1);
    cudaGetSymbolAddress((void**)&hq0, g_hq0);
    cudaGetSymbolAddress((void**)&hs,  g_hs);
    cudaGetSymbolAddress((void**)&y2,  g_y2);

    zero_counts_kernel<<<1, 32>>>();
    router_kernel<<<B_TOK, 256>>>(x, gw, gb);
    scan_kernel<<<1, 32>>>();
    scatter_kernel<<<(NSLOT + 255) / 256, 256>>>();

    xquant_kernel<<<B_TOK, 256>>>(x);
    wquant_kernel<<<dim3(H_DIM / 128, 1, E_EXP), 256>>>(w1, w1q1, w1q0, w1s, D_DIM, H_DIM);
    wquant_kernel<<<dim3(O_DIM / 128, 1, E_EXP), 256>>>(w2, w2q1, w2q0, w2s, H_DIM, O_DIM);

    // layer 1: gathered xq @ w1q -> bias/relu -> bf16-pair h
    moe_gemm_imma<0><<<dim3(H_DIM / 128, 32, E_EXP), 256, GEMM_SMEM>>>(
        xq1, xq0, xs, w1q1, w1q0, w1s, b1, nullptr, D_DIM, H_DIM);
    hquant_kernel<<<NSLOT, 256>>>();
    // layer 2: hq @ w2q -> bias -> per-slot fp32
    moe_gemm_imma<1><<<dim3(O_DIM / 128, 32, E_EXP), 256, GEMM_SMEM>>>(
        hq1, hq0, hs, w2q1, w2q0, w2s, b2, y2, H_DIM, O_DIM);
    combine_kernel<<<B_TOK, 256>>>(y);
}

// round 6
// speedup vs baseline: 3.2532x; 3.2532x over previous
#include <cuda_runtime.h>
#include <cuda_bf16.h>
#include <cstdint>

#define B_TOK 4096
#define D_DIM 1024
#define O_DIM 1024
#define E_EXP 8
#define H_DIM 4096
#define NSLOT (B_TOK * 2)

// ---------------- scratch ----------------
__device__ int   g_counts[E_EXP];
__device__ int   g_off[E_EXP + 1];
__device__ int   g_eidx[NSLOT];
__device__ int   g_epos[NSLOT];
__device__ float g_ew[NSLOT];
__device__ int   g_slot[NSLOT];
__device__ int   g_perm[NSLOT];

__device__ __nv_bfloat16 g_xh[(size_t)B_TOK * D_DIM];
__device__ __nv_bfloat16 g_xl[(size_t)B_TOK * D_DIM];
__device__ __nv_bfloat16 g_w1h[(size_t)E_EXP * D_DIM * H_DIM];
__device__ __nv_bfloat16 g_w1l[(size_t)E_EXP * D_DIM * H_DIM];
__device__ __nv_bfloat16 g_w2h[(size_t)E_EXP * H_DIM * O_DIM];
__device__ __nv_bfloat16 g_w2l[(size_t)E_EXP * H_DIM * O_DIM];
__device__ __nv_bfloat16 g_hh[(size_t)NSLOT * H_DIM];
__device__ __nv_bfloat16 g_hl[(size_t)NSLOT * H_DIM];
__device__ float g_y2[(size_t)NSLOT * O_DIM];

// ---------------- PTX helpers ----------------
__device__ __forceinline__ uint32_t smem_u32(const void* p) {
    uint32_t a;
    asm("{ .reg .u64 t; cvta.to.shared.u64 t, %1; cvt.u32.u64 %0, t; }" : "=r"(a) : "l"(p));
    return a;
}
__device__ __forceinline__ void cpa16(uint32_t dst, const void* src) {
    asm volatile("cp.async.cg.shared.global [%0], [%1], 16;\n" :: "r"(dst), "l"(src));
}
#define CP_COMMIT() asm volatile("cp.async.commit_group;" ::: "memory")
template<int N> __device__ __forceinline__ void cp_wait() {
    asm volatile("cp.async.wait_group %0;" :: "n"(N) : "memory");
}

#define LDSM_X4(r0, r1, r2, r3, a) \
    asm volatile("ldmatrix.sync.aligned.m8n8.x4.shared.b16 {%0,%1,%2,%3}, [%4];" \
                 : "=r"(r0), "=r"(r1), "=r"(r2), "=r"(r3) : "r"(a))
#define LDSM_X4T(r0, r1, r2, r3, a) \
    asm volatile("ldmatrix.sync.aligned.m8n8.x4.trans.shared.b16 {%0,%1,%2,%3}, [%4];" \
                 : "=r"(r0), "=r"(r1), "=r"(r2), "=r"(r3) : "r"(a))

__device__ __forceinline__ void mma_bf16(float* c, const uint32_t* a, const uint32_t* b) {
    asm volatile(
        "mma.sync.aligned.m16n8k16.row.col.f32.bf16.bf16.f32 "
        "{%0,%1,%2,%3}, {%4,%5,%6,%7}, {%8,%9}, {%0,%1,%2,%3};"
        : "+f"(c[0]), "+f"(c[1]), "+f"(c[2]), "+f"(c[3])
        : "r"(a[0]), "r"(a[1]), "r"(a[2]), "r"(a[3]), "r"(b[0]), "r"(b[1]));
}

// ---------------- routing ----------------
__global__ void zero_counts_kernel() {
    if (threadIdx.x < E_EXP) g_counts[threadIdx.x] = 0;
}

__global__ void router_kernel(const float* __restrict__ x,
                              const float* __restrict__ gw,
                              const float* __restrict__ gb) {
    int b = blockIdx.x, tid = threadIdx.x;
    int e = tid & 7, ds = tid >> 3;
    const float* xr = x + (size_t)b * D_DIM;
    float p = 0.f;
    #pragma unroll 4
    for (int d = ds; d < D_DIM; d += 32) p += xr[d] * gw[d * E_EXP + e];
    __shared__ float red[256];
    red[tid] = p;
    __syncthreads();
    #pragma unroll
    for (int s = 128; s >= 8; s >>= 1) {
        if (tid < s) red[tid] += red[tid + s];
        __syncthreads();
    }
    if (tid == 0) {
        float v0 = -1e30f, v1 = -1e30f; int i0 = 0, i1 = 0;
        #pragma unroll
        for (int ee = 0; ee < E_EXP; ee++) {
            float v = red[ee] + gb[ee];
            if (v > v0) { v1 = v0; i1 = i0; v0 = v; i0 = ee; }
            else if (v > v1) { v1 = v; i1 = ee; }
        }
        float ex = expf(v1 - v0), inv = 1.f / (1.f + ex);
        int p0 = atomicAdd(&g_counts[i0], 1);
        int p1 = atomicAdd(&g_counts[i1], 1);
        g_eidx[b*2+0] = i0; g_epos[b*2+0] = p0; g_ew[b*2+0] = inv;
        g_eidx[b*2+1] = i1; g_epos[b*2+1] = p1; g_ew[b*2+1] = ex * inv;
    }
}

__global__ void scan_kernel() {
    if (threadIdx.x == 0) {
        int acc = 0;
        #pragma unroll
        for (int e = 0; e < E_EXP; e++) { g_off[e] = acc; acc += g_counts[e]; }
        g_off[E_EXP] = acc;
    }
}

__global__ void scatter_kernel() {
    int i = blockIdx.x * blockDim.x + threadIdx.x;
    if (i >= NSLOT) return;
    int slot = g_off[g_eidx[i]] + g_epos[i];
    g_slot[i] = slot;
    g_perm[slot] = i >> 1;
}

// ---------------- precision split ----------------
__device__ __forceinline__ void split_bf16(float v, __nv_bfloat16& h, __nv_bfloat16& l) {
    h = __float2bfloat16(v);
    l = __float2bfloat16(v - __bfloat162float(h));
}

__global__ void convert_split_kernel(const float* __restrict__ src,
                                     __nv_bfloat16* __restrict__ oh,
                                     __nv_bfloat16* __restrict__ ol) {
    size_t i = ((size_t)blockIdx.x * 256 + threadIdx.x) * 4;
    float4 v = *(const float4*)(src + i);
    __nv_bfloat16 h, l;
    split_bf16(v.x, h, l); oh[i+0] = h; ol[i+0] = l;
    split_bf16(v.y, h, l); oh[i+1] = h; ol[i+1] = l;
    split_bf16(v.z, h, l); oh[i+2] = h; ol[i+2] = l;
    split_bf16(v.w, h, l); oh[i+3] = h; ol[i+3] = l;
}

// ---------------- HMMA grouped GEMM ----------------
// CTA 128x128xBK32, 8 warps 2x4, warp tile 64x32, bf16 m16n8k16, 3 passes.
// Stage: Ah 8K | Al 8K | Bh 8K | Bl 8K = 32KB; 3 stages = 96KB -> 2 CTAs/SM.
// Single-sync pipeline: prologue 2 chunks; per-iter wait<=1, sync, prefetch c+2.
#define STAGES 3
#define STAGE_BYTES 32768
#define GEMM_SMEM (STAGES * STAGE_BYTES)

template <int MODE>
__global__ __launch_bounds__(256, 2)
void moe_gemm_hmma(const __nv_bfloat16* __restrict__ Ah_base,
                   const __nv_bfloat16* __restrict__ Al_base,
                   const __nv_bfloat16* __restrict__ Wh_base,
                   const __nv_bfloat16* __restrict__ Wl_base,
                   const float* __restrict__ bias,
                   float* __restrict__ yout,
                   int KD, int ND) {
    int e   = blockIdx.z;
    int cnt = g_counts[e];
    int m0  = blockIdx.y * 128;
    if (m0 >= cnt) return;
    int off = g_off[e];
    int n0  = blockIdx.x * 128;

    extern __shared__ char dsm[];
    __shared__ int s_arow[128];

    int tid  = threadIdx.x;
    int wid  = tid >> 5, lane = tid & 31;
    int wm   = (wid >> 2) * 64;
    int wn   = (wid & 3) * 32;
    int g    = lane >> 2, t4 = lane & 3;

    const __nv_bfloat16* Wh = Wh_base + (size_t)e * KD * ND;
    const __nv_bfloat16* Wl = Wl_base + (size_t)e * KD * ND;

    if (tid < 128) {
        int r = m0 + tid;
        int src = 0;
        if (r < cnt) src = (MODE == 0) ? g_perm[off + r] : (off + r);
        s_arow[tid] = src;
    }
    __syncthreads();

    uint32_t smb = smem_u32(dsm);
    const int NC = KD >> 5;

    auto load_stage = [&](int c) {
        uint32_t sb = smb + (c % STAGES) * STAGE_BYTES;
        int k0 = c << 5;
        #pragma unroll
        for (int t = 0; t < 2; t++) {
            int cid = tid + t * 256;
            int row = cid >> 2, seg = cid & 3;
            uint32_t so = (uint32_t)(row * 64 + seg * 16) ^ (((uint32_t)row & 7u) << 4);
            size_t ao = (size_t)s_arow[row] * KD + k0 + seg * 8;
            cpa16(sb + so,        Ah_base + ao);
            cpa16(sb + 8192 + so, Al_base + ao);
        }
        #pragma unroll
        for (int t = 0; t < 2; t++) {
            int cid = tid + t * 256;
            int k = cid >> 4, nseg = cid & 15;
            uint32_t so = (uint32_t)(k * 256 + nseg * 16) ^ (((uint32_t)k & 7u) << 4);
            size_t bo = (size_t)(k0 + k) * ND + n0 + nseg * 8;
            cpa16(sb + 16384 + so, Wh + bo);
            cpa16(sb + 24576 + so, Wl + bo);
        }
        CP_COMMIT();
    };

    // prologue: only 2 chunks in flight
    load_stage(0);
    if (NC > 1) load_stage(1);

    float acc[4][4][4];
    #pragma unroll
    for (int i = 0; i < 4; i++)
        #pragma unroll
        for (int j = 0; j < 4; j++)
            #pragma unroll
            for (int q = 0; q < 4; q++) acc[i][j][q] = 0.f;

    for (int c = 0; c < NC; c++) {
        // ensure chunk c resident (chunk c+1 may remain in flight)
        if (c + 1 < NC) cp_wait<1>(); else cp_wait<0>();
        __syncthreads();   // all warps done reading stage (c-1)%3 -> safe to refill
        // prefetch chunk c+2 into stage (c+2)%3 == (c-1)%3 BEFORE compute
        if (c + 2 < NC) load_stage(c + 2);

        uint32_t sb = smb + (c % STAGES) * STAGE_BYTES;

        #pragma unroll
        for (int ks = 0; ks < 2; ks++) {
            uint32_t bh[8], bl[8];
            int kk = ks * 16 + (lane & 7) + ((lane >> 3) & 1) * 8;
            #pragma unroll
            for (int nf2 = 0; nf2 < 2; nf2++) {
                int noct = (wid & 3) * 4 + nf2 * 2 + (lane >> 4);
                uint32_t so = (uint32_t)(kk * 256 + noct * 16) ^ (((uint32_t)kk & 7u) << 4);
                LDSM_X4T(bh[nf2*4+0], bh[nf2*4+1], bh[nf2*4+2], bh[nf2*4+3], sb + 16384 + so);
                LDSM_X4T(bl[nf2*4+0], bl[nf2*4+1], bl[nf2*4+2], bl[nf2*4+3], sb + 24576 + so);
            }
            #pragma unroll
            for (int mf = 0; mf < 4; mf++) {
                int row = wm + mf * 16 + (lane & 7) + ((lane >> 3) & 1) * 8;
                int seg = ks * 2 + ((lane >> 4) & 1);
                uint32_t so = (uint32_t)(row * 64 + seg * 16) ^ (((uint32_t)row & 7u) << 4);
                uint32_t ah[4], al[4];
                LDSM_X4(ah[0], ah[1], ah[2], ah[3], sb + so);
                LDSM_X4(al[0], al[1], al[2], al[3], sb + 8192 + so);
                #pragma unroll
                for (int nf = 0; nf < 4; nf++) {
                    mma_bf16(acc[mf][nf], ah, &bh[nf*2]);
                    mma_bf16(acc[mf][nf], ah, &bl[nf*2]);
                    mma_bf16(acc[mf][nf], al, &bh[nf*2]);
                }
            }
        }
        // no trailing sync: next iteration's sync protects stage reuse
    }

    // ---------------- epilogue (no atomics) ----------------
    float bias0[4], bias1[4];
    #pragma unroll
    for (int nf = 0; nf < 4; nf++) {
        int n = n0 + wn + nf * 8 + t4 * 2;
        bias0[nf] = bias[e * ND + n];
        bias1[nf] = bias[e * ND + n + 1];
    }

    #pragma unroll
    for (int mf = 0; mf < 4; mf++) {
        #pragma unroll
        for (int half = 0; half < 2; half++) {
            int r = m0 + wm + mf * 16 + g + half * 8;
            if (r >= cnt) continue;
            size_t rb = (size_t)(off + r) * ND + n0 + wn + t4 * 2;
            if (MODE == 0) {
                #pragma unroll
                for (int nf = 0; nf < 4; nf++) {
                    float v0 = acc[mf][nf][half*2+0] + bias0[nf];
                    float v1 = acc[mf][nf][half*2+1] + bias1[nf];
                    v0 = v0 > 0.f ? v0 : 0.f;
                    v1 = v1 > 0.f ? v1 : 0.f;
                    __nv_bfloat16 h0, l0, h1, l1;
                    split_bf16(v0, h0, l0);
                    split_bf16(v1, h1, l1);
                    *(__nv_bfloat162*)(g_hh + rb + nf * 8) = __nv_bfloat162(h0, h1);
                    *(__nv_bfloat162*)(g_hl + rb + nf * 8) = __nv_bfloat162(l0, l1);
                }
            } else {
                #pragma unroll
                for (int nf = 0; nf < 4; nf++) {
                    float2 v;
                    v.x = acc[mf][nf][half*2+0] + bias0[nf];
                    v.y = acc[mf][nf][half*2+1] + bias1[nf];
                    *(float2*)(yout + rb + nf * 8) = v;
                }
            }
        }
    }
}

// ---------------- combine: y[b] = w0*y2[slot0] + w1*y2[slot1] ----------------
__global__ void combine_kernel(float* __restrict__ y) {
    int b = blockIdx.x, t = threadIdx.x;
    int s0 = g_slot[b*2+0], s1 = g_slot[b*2+1];
    float w0 = g_ew[b*2+0], w1 = g_ew[b*2+1];
    float4 a = *(const float4*)(g_y2 + (size_t)s0 * O_DIM + t * 4);
    float4 c = *(const float4*)(g_y2 + (size_t)s1 * O_DIM + t * 4);
    float4 o;
    o.x = w0 * a.x + w1 * c.x;
    o.y = w0 * a.y + w1 * c.y;
    o.z = w0 * a.z + w1 * c.z;
    o.w = w0 * a.w + w1 * c.w;
    *(float4*)(y + (size_t)b * O_DIM + t * 4) = o;
}

// ---------------- launch ----------------
extern "C" void kernel_launch(void* const* d_in, const int* in_sizes, int n_in,
                              void* d_out, int out_size) {
    const float* x  = (const float*)d_in[0];
    const float* gw = (const float*)d_in[1];
    const float* gb = (const float*)d_in[2];
    const float* w1 = (const float*)d_in[3];
    const float* b1 = (const float*)d_in[4];
    const float* w2 = (const float*)d_in[5];
    const float* b2 = (const float*)d_in[6];
    float* y = (float*)d_out;

    cudaFuncSetAttribute(moe_gemm_hmma<0>, cudaFuncAttributeMaxDynamicSharedMemorySize, GEMM_SMEM);
    cudaFuncSetAttribute(moe_gemm_hmma<1>, cudaFuncAttributeMaxDynamicSharedMemorySize, GEMM_SMEM);

    __nv_bfloat16 *xh, *xl, *w1h, *w1l, *w2h, *w2l, *hh, *hl;
    float* y2;
    cudaGetSymbolAddress((void**)&xh,  g_xh);
    cudaGetSymbolAddress((void**)&xl,  g_xl);
    cudaGetSymbolAddress((void**)&w1h, g_w1h);
    cudaGetSymbolAddress((void**)&w1l, g_w1l);
    cudaGetSymbolAddress((void**)&w2h, g_w2h);
    cudaGetSymbolAddress((void**)&w2l, g_w2l);
    cudaGetSymbolAddress((void**)&hh,  g_hh);
    cudaGetSymbolAddress((void**)&hl,  g_hl);
    cudaGetSymbolAddress((void**)&y2,  g_y2);

    zero_counts_kernel<<<1, 32>>>();
    router_kernel<<<B_TOK, 256>>>(x, gw, gb);
    scan_kernel<<<1, 32>>>();
    scatter_kernel<<<(NSLOT + 255) / 256, 256>>>();

    convert_split_kernel<<<(B_TOK * D_DIM) / 1024, 256>>>(x, xh, xl);
    convert_split_kernel<<<(E_EXP * D_DIM * H_DIM) / 1024, 256>>>(w1, w1h, w1l);
    convert_split_kernel<<<(E_EXP * H_DIM * O_DIM) / 1024, 256>>>(w2, w2h, w2l);

    moe_gemm_hmma<0><<<dim3(H_DIM / 128, 32, E_EXP), 256, GEMM_SMEM>>>(
        xh, xl, w1h, w1l, b1, nullptr, D_DIM, H_DIM);
    moe_gemm_hmma<1><<<dim3(O_DIM / 128, 32, E_EXP), 256, GEMM_SMEM>>>(
        hh, hl, w2h, w2l, b2, y2, H_DIM, O_DIM);
    combine_kernel<<<B_TOK, 256>>>(y);
}